// round 15
// baseline (speedup 1.0000x reference)
#include <cuda_runtime.h>
#include <cuda_fp16.h>

#define NB 50000
#define EE 1600000
#define ET (EE + NB)
#define GG 128

// ---------------- device scratch (no allocations allowed) ----------------
__device__ __align__(16) int    g_csr[ET];          // src ids sorted by dst
__device__ __align__(16) int    g_deg[NB + 1];
__device__ __align__(16) int    g_off[NB + 1];
__device__ __align__(16) int    g_cur[NB];
__device__ __align__(16) __half g_h16[NB * 64];     // W-transformed features (fp16, agg-only)
__device__ __align__(16) float  g_act[NB * 64];     // activated layer output / next input
__device__ __align__(16) float  g_asrc[NB * 8];
__device__ __align__(16) float  g_adst[NB * 8];
__device__ __align__(16) float  g_pool[GG * 32];
__device__ __align__(16) float  g_cnt[GG];

// ---------------- graph build ----------------
__global__ void k_zero() {
    int i = blockIdx.x * blockDim.x + threadIdx.x;
    if (i <= NB) g_deg[i] = 0;
    if (i < GG * 32) g_pool[i] = 0.f;
    if (i < GG) g_cnt[i] = 0.f;
}

__global__ void k_count(const int* __restrict__ ei) {
    int i = blockIdx.x * blockDim.x + threadIdx.x;
    if (i >= ET) return;
    int d = (i < EE) ? ei[EE + i] : (i - EE);
    atomicAdd(&g_deg[d], 1);
}

__global__ void k_scan() {   // 1 block, 1024 threads: exclusive scan of g_deg
    __shared__ int sm[1024];
    const int C = 49;                       // 49*1024 >= NB
    int t = threadIdx.x;
    int start = t * C;
    int end = min(start + C, NB);
    int sum = 0;
    for (int i = start; i < end; i++) sum += g_deg[i];
    sm[t] = sum;
    __syncthreads();
    for (int d = 1; d < 1024; d <<= 1) {
        int v = (t >= d) ? sm[t - d] : 0;
        __syncthreads();
        sm[t] += v;
        __syncthreads();
    }
    int run = (t == 0) ? 0 : sm[t - 1];
    for (int i = start; i < end; i++) {
        g_off[i] = run; g_cur[i] = run;
        run += g_deg[i];
    }
    if (t == 0) g_off[NB] = sm[1023];
}

__global__ void k_scatter(const int* __restrict__ ei) {
    int i = blockIdx.x * blockDim.x + threadIdx.x;
    if (i >= ET) return;
    int s, d;
    if (i < EE) { s = ei[i]; d = ei[EE + i]; }
    else        { s = i - EE; d = s; }
    int pos = atomicAdd(&g_cur[d], 1);
    g_csr[pos] = s;
}

// ---------------- dense: h = X @ W  + fused attn-coef epilogue + fp16 h store ----
template <int K, int J, int RB, bool USE_ACT>
__global__ void k_gemm(const float* __restrict__ Xparam, const float* __restrict__ W,
                       const float* __restrict__ As, const float* __restrict__ Ad) {
    const float* __restrict__ X = USE_ACT ? (const float*)g_act : Xparam;
    constexpr int CG = J / 4;                 // column groups (4 contiguous cols)
    constexpr int RPT = RB * CG / 256;        // rows per thread
    __shared__ float sW[K * J];
    __shared__ float sX[RB * K];
    int t = threadIdx.x;
    int row0 = blockIdx.x * RB;
    for (int i = t; i < K * J; i += 256) sW[i] = W[i];
    int nrows = min(RB, NB - row0);
    for (int i = t; i < nrows * K; i += 256) sX[i] = X[(size_t)row0 * K + i];
    __syncthreads();

    int rg = t / CG, cg = t % CG;
    float acc[RPT][4];
#pragma unroll
    for (int r = 0; r < RPT; r++)
#pragma unroll
        for (int q = 0; q < 4; q++) acc[r][q] = 0.f;

#pragma unroll 8
    for (int k = 0; k < K; k++) {
        float4 w = *(const float4*)&sW[k * J + cg * 4];
#pragma unroll
        for (int r = 0; r < RPT; r++) {
            float xv = sX[(rg * RPT + r) * K + k];
            acc[r][0] = fmaf(xv, w.x, acc[r][0]);
            acc[r][1] = fmaf(xv, w.y, acc[r][1]);
            acc[r][2] = fmaf(xv, w.z, acc[r][2]);
            acc[r][3] = fmaf(xv, w.w, acc[r][3]);
        }
    }

    // attention-coefficient vectors for this thread's 4 columns
    float4 asv, adv;
    if (J == 64) {
        int h = cg >> 1;
        asv = __ldg((const float4*)(As + h * 8 + (cg & 1) * 4));
        adv = __ldg((const float4*)(Ad + h * 8 + (cg & 1) * 4));
    } else {
        asv = __ldg((const float4*)(As + cg * 4));
        adv = __ldg((const float4*)(Ad + cg * 4));
    }

#pragma unroll
    for (int r = 0; r < RPT; r++) {
        float pa = acc[r][0]*asv.x + acc[r][1]*asv.y + acc[r][2]*asv.z + acc[r][3]*asv.w;
        float pd = acc[r][0]*adv.x + acc[r][1]*adv.y + acc[r][2]*adv.z + acc[r][3]*adv.w;
        if (J == 64) {
            pa += __shfl_xor_sync(0xffffffffu, pa, 1);
            pd += __shfl_xor_sync(0xffffffffu, pd, 1);
        } else {
#pragma unroll
            for (int ofs = 1; ofs < 8; ofs <<= 1) {
                pa += __shfl_xor_sync(0xffffffffu, pa, ofs);
                pd += __shfl_xor_sync(0xffffffffu, pd, ofs);
            }
        }
        int row = row0 + rg * RPT + r;
        if (row < NB) {
            union { __half2 h2[2]; uint2 u2; } pk;
            pk.h2[0] = __floats2half2_rn(acc[r][0], acc[r][1]);
            pk.h2[1] = __floats2half2_rn(acc[r][2], acc[r][3]);
            *(uint2*)(g_h16 + (size_t)row * J + cg * 4) = pk.u2;
            if (J == 64) {
                if ((cg & 1) == 0) {
                    int h = cg >> 1;
                    g_asrc[row * 8 + h] = pa;
                    g_adst[row * 8 + h] = pd;
                }
            } else {
                if (cg == 0) { g_asrc[row] = pa; g_adst[row] = pd; }
            }
        }
    }
}

// ---------------- softmax-aggregate: warp per dst node, single pass ----------------
__global__ void k_agg(const float* __restrict__ B) {
    int gw = (blockIdx.x * blockDim.x + threadIdx.x) >> 5;
    if (gw >= NB) return;
    int lane = threadIdx.x & 31;
    int head = lane >> 2;
    int begin = g_off[gw], end = g_off[gw + 1];
    float ad = g_adst[gw * 8 + head];
    int j = lane * 2;                              // channel pair: head*8 + (lane%4)*2
    const __half2* __restrict__ h2p = (const __half2*)g_h16;

    float s = 0.f, ax = 0.f, ay = 0.f;
    for (int i = begin; i < end; i++) {
        int src = __ldg(&g_csr[i]);
        float e = __ldg(&g_asrc[src * 8 + head]) + ad;
        e = (e >= 0.f) ? e : 0.2f * e;
        float p = __expf(fminf(e, 80.f));
        float2 hv = __half22float2(__ldg(&h2p[src * 32 + lane]));
        s += p;
        ax = fmaf(p, hv.x, ax);
        ay = fmaf(p, hv.y, ay);
    }
    float inv = 1.f / (s + 1e-16f);
    float ox = ax * inv + B[j];
    float oy = ay * inv + B[j + 1];
    ox = (ox > 0.f) ? ox : (__expf(ox) - 1.f);     // ELU
    oy = (oy > 0.f) ? oy : (__expf(oy) - 1.f);
    *(float2*)(g_act + (size_t)gw * 64 + j) = make_float2(ox, oy);
}

// single pass + fused global mean-pool accumulation
__global__ void k_agg_final(const float* __restrict__ Bf, const int* __restrict__ batch) {
    int gw = (blockIdx.x * blockDim.x + threadIdx.x) >> 5;
    if (gw >= NB) return;
    int lane = threadIdx.x & 31;
    int begin = g_off[gw], end = g_off[gw + 1];
    float ad = g_adst[gw];

    float s = 0.f, acc = 0.f;
    for (int i = begin; i < end; i++) {
        int src = __ldg(&g_csr[i]);
        float e = __ldg(&g_asrc[src]) + ad;
        e = (e >= 0.f) ? e : 0.2f * e;
        float p = __expf(fminf(e, 80.f));
        s += p;
        float hv = __half2float(__ldg(&g_h16[(size_t)src * 32 + lane]));
        acc = fmaf(p, hv, acc);
    }
    float o = acc / (s + 1e-16f) + Bf[lane];
    int g = batch[gw];
    atomicAdd(&g_pool[g * 32 + lane], o);
    if (lane == 0) atomicAdd(&g_cnt[g], 1.f);
}

// ---------------- head ----------------
__global__ void k_final(const float* __restrict__ Wl, const float* __restrict__ bl,
                        float* __restrict__ out) {
    int t = blockIdx.x * blockDim.x + threadIdx.x;
    if (t >= GG * 2) return;
    int g = t >> 1, o = t & 1;
    float cnt = fmaxf(g_cnt[g], 1.f);
    float acc = 0.f;
#pragma unroll
    for (int c = 0; c < 32; c++) acc += g_pool[g * 32 + c] * Wl[c * 2 + o];
    out[t] = acc / cnt + bl[o];
}

// ---------------- launcher ----------------
// INSTRUMENTATION ROUND:
//  - gemm0 moved before k_scatter (no dependency) so the fixed ncu window
//    (empirically: 4th launch) profiles the GEMM for the first time.
//  - k_agg layers 1 and 2 are launched twice (idempotent: same inputs ->
//    same g_act). dur_us = best(426) + 2 * t_agg, measuring the warm agg cost.
extern "C" void kernel_launch(void* const* d_in, const int* in_sizes, int n_in,
                              void* d_out, int out_size) {
    const float* x     = (const float*)d_in[0];
    const int*   ei    = (const int*)d_in[1];      // int32
    const int*   batch = (const int*)d_in[2];      // int32
    const float* W0 = (const float*)d_in[3];
    const float* as0 = (const float*)d_in[4];
    const float* ad0 = (const float*)d_in[5];
    const float* b0 = (const float*)d_in[6];
    const float* W1 = (const float*)d_in[7];
    const float* as1 = (const float*)d_in[8];
    const float* ad1 = (const float*)d_in[9];
    const float* b1 = (const float*)d_in[10];
    const float* W2 = (const float*)d_in[11];
    const float* as2 = (const float*)d_in[12];
    const float* ad2 = (const float*)d_in[13];
    const float* b2 = (const float*)d_in[14];
    const float* Wf = (const float*)d_in[15];
    const float* asf = (const float*)d_in[16];
    const float* adf = (const float*)d_in[17];
    const float* bf = (const float*)d_in[18];
    const float* Wl = (const float*)d_in[19];
    const float* bl = (const float*)d_in[20];
    float* out = (float*)d_out;

    const int AGG_GRID = (NB * 32 + 255) / 256;

    // graph prep + layer-0 GEMM (gemm0 is CSR-independent; placed 4th for ncu)
    k_zero<<<(NB + 256) / 256, 256>>>();
    k_count<<<(ET + 255) / 256, 256>>>(ei);
    k_scan<<<1, 1024>>>();
    k_gemm<128, 64, 32, false><<<(NB + 31) / 32, 256>>>(x, W0, as0, ad0);
    k_scatter<<<(ET + 255) / 256, 256>>>(ei);

    // layer 0 aggregate
    k_agg<<<AGG_GRID, 256>>>(b0);
    // layer 1
    k_gemm<64, 64, 64, true><<<(NB + 63) / 64, 256>>>(nullptr, W1, as1, ad1);
    k_agg<<<AGG_GRID, 256>>>(b1);
    k_agg<<<AGG_GRID, 256>>>(b1);      // duplicate (timing probe)
    // layer 2
    k_gemm<64, 64, 64, true><<<(NB + 63) / 64, 256>>>(nullptr, W2, as2, ad2);
    k_agg<<<AGG_GRID, 256>>>(b2);
    k_agg<<<AGG_GRID, 256>>>(b2);      // duplicate (timing probe)
    // final conv: 64 -> 32, 1 head
    k_gemm<64, 32, 64, true><<<(NB + 63) / 64, 256>>>(nullptr, Wf, asf, adf);
    k_agg_final<<<AGG_GRID, 256>>>(bf, batch);

    // linear head
    k_final<<<1, 256>>>(Wl, bl, out);
}

// round 16
// speedup vs baseline: 1.3892x; 1.3892x over previous
#include <cuda_runtime.h>
#include <cuda_fp16.h>

#define NB 50000
#define EE 1600000
#define ET (EE + NB)
#define GG 128

// ---------------- device scratch (no allocations allowed) ----------------
__device__ __align__(16) int    g_csr[ET];          // src ids sorted by dst
__device__ __align__(16) int    g_deg[NB + 1];
__device__ __align__(16) int    g_off[NB + 1];
__device__ __align__(16) int    g_cur[NB];
__device__ __align__(16) __half g_h16[NB * 64];     // W-transformed features (fp16, agg-only)
__device__ __align__(16) float  g_act[NB * 64];     // activated layer output / next input
__device__ __align__(16) float  g_asrc[NB * 8];
__device__ __align__(16) float  g_adst[NB * 8];
__device__ __align__(16) float  g_pool[GG * 32];
__device__ __align__(16) float  g_cnt[GG];

// ---------------- graph build ----------------
__global__ void k_zero() {
    int i = blockIdx.x * blockDim.x + threadIdx.x;
    if (i <= NB) g_deg[i] = 0;
    if (i < GG * 32) g_pool[i] = 0.f;
    if (i < GG) g_cnt[i] = 0.f;
}

__global__ void k_count(const int* __restrict__ ei) {
    int i = blockIdx.x * blockDim.x + threadIdx.x;
    if (i >= ET) return;
    int d = (i < EE) ? ei[EE + i] : (i - EE);
    atomicAdd(&g_deg[d], 1);
}

__global__ void k_scan() {   // 1 block, 1024 threads: exclusive scan of g_deg
    __shared__ int sm[1024];
    const int C = 49;                       // 49*1024 >= NB
    int t = threadIdx.x;
    int start = t * C;
    int end = min(start + C, NB);
    int sum = 0;
    for (int i = start; i < end; i++) sum += g_deg[i];
    sm[t] = sum;
    __syncthreads();
    for (int d = 1; d < 1024; d <<= 1) {
        int v = (t >= d) ? sm[t - d] : 0;
        __syncthreads();
        sm[t] += v;
        __syncthreads();
    }
    int run = (t == 0) ? 0 : sm[t - 1];
    for (int i = start; i < end; i++) {
        g_off[i] = run; g_cur[i] = run;
        run += g_deg[i];
    }
    if (t == 0) g_off[NB] = sm[1023];
}

__global__ void k_scatter(const int* __restrict__ ei) {
    int i = blockIdx.x * blockDim.x + threadIdx.x;
    if (i >= ET) return;
    int s, d;
    if (i < EE) { s = ei[i]; d = ei[EE + i]; }
    else        { s = i - EE; d = s; }
    int pos = atomicAdd(&g_cur[d], 1);
    g_csr[pos] = s;
}

// ---------------- dense: h = X @ W  + fused attn-coef epilogue + fp16 h store ----
template <int K, int J, int RB, bool USE_ACT>
__global__ void k_gemm(const float* __restrict__ Xparam, const float* __restrict__ W,
                       const float* __restrict__ As, const float* __restrict__ Ad) {
    const float* __restrict__ X = USE_ACT ? (const float*)g_act : Xparam;
    constexpr int CG = J / 4;                 // column groups (4 contiguous cols)
    constexpr int RPT = RB * CG / 256;        // rows per thread
    __shared__ float sW[K * J];
    __shared__ float sX[RB * K];
    int t = threadIdx.x;
    int row0 = blockIdx.x * RB;
    for (int i = t; i < K * J; i += 256) sW[i] = W[i];
    int nrows = min(RB, NB - row0);
    for (int i = t; i < nrows * K; i += 256) sX[i] = X[(size_t)row0 * K + i];
    __syncthreads();

    int rg = t / CG, cg = t % CG;
    float acc[RPT][4];
#pragma unroll
    for (int r = 0; r < RPT; r++)
#pragma unroll
        for (int q = 0; q < 4; q++) acc[r][q] = 0.f;

#pragma unroll 8
    for (int k = 0; k < K; k++) {
        float4 w = *(const float4*)&sW[k * J + cg * 4];
#pragma unroll
        for (int r = 0; r < RPT; r++) {
            float xv = sX[(rg * RPT + r) * K + k];
            acc[r][0] = fmaf(xv, w.x, acc[r][0]);
            acc[r][1] = fmaf(xv, w.y, acc[r][1]);
            acc[r][2] = fmaf(xv, w.z, acc[r][2]);
            acc[r][3] = fmaf(xv, w.w, acc[r][3]);
        }
    }

    // attention-coefficient vectors for this thread's 4 columns
    float4 asv, adv;
    if (J == 64) {
        int h = cg >> 1;
        asv = __ldg((const float4*)(As + h * 8 + (cg & 1) * 4));
        adv = __ldg((const float4*)(Ad + h * 8 + (cg & 1) * 4));
    } else {
        asv = __ldg((const float4*)(As + cg * 4));
        adv = __ldg((const float4*)(Ad + cg * 4));
    }

#pragma unroll
    for (int r = 0; r < RPT; r++) {
        float pa = acc[r][0]*asv.x + acc[r][1]*asv.y + acc[r][2]*asv.z + acc[r][3]*asv.w;
        float pd = acc[r][0]*adv.x + acc[r][1]*adv.y + acc[r][2]*adv.z + acc[r][3]*adv.w;
        if (J == 64) {
            pa += __shfl_xor_sync(0xffffffffu, pa, 1);
            pd += __shfl_xor_sync(0xffffffffu, pd, 1);
        } else {
#pragma unroll
            for (int ofs = 1; ofs < 8; ofs <<= 1) {
                pa += __shfl_xor_sync(0xffffffffu, pa, ofs);
                pd += __shfl_xor_sync(0xffffffffu, pd, ofs);
            }
        }
        int row = row0 + rg * RPT + r;
        if (row < NB) {
            union { __half2 h2[2]; uint2 u2; } pk;
            pk.h2[0] = __floats2half2_rn(acc[r][0], acc[r][1]);
            pk.h2[1] = __floats2half2_rn(acc[r][2], acc[r][3]);
            *(uint2*)(g_h16 + (size_t)row * J + cg * 4) = pk.u2;
            if (J == 64) {
                if ((cg & 1) == 0) {
                    int h = cg >> 1;
                    g_asrc[row * 8 + h] = pa;
                    g_adst[row * 8 + h] = pd;
                }
            } else {
                if (cg == 0) { g_asrc[row] = pa; g_adst[row] = pd; }
            }
        }
    }
}

// ---------------- softmax-aggregate: warp per dst node, 2 edges/iteration -------
// Half-warps process alternating edges; each lane covers 4 channels (8B load).
// Halves per-edge issue cost (loop overhead, MUFU, p-redundancy) vs 1-edge form.
__global__ void k_agg(const float* __restrict__ B) {
    int gw = (blockIdx.x * blockDim.x + threadIdx.x) >> 5;
    if (gw >= NB) return;
    int lane = threadIdx.x & 31;
    int half = lane >> 4;           // 0: even edges, 1: odd edges
    int cl   = lane & 15;           // channels 4cl..4cl+3
    int head = cl >> 1;
    int begin = g_off[gw], end = g_off[gw + 1];
    float ad = g_adst[gw * 8 + head];

    float s = 0.f, a0 = 0.f, a1 = 0.f, a2 = 0.f, a3 = 0.f;
    for (int i = begin + half; i < end; i += 2) {
        int src = __ldg(&g_csr[i]);
        float e = __ldg(&g_asrc[src * 8 + head]) + ad;
        e = (e >= 0.f) ? e : 0.2f * e;
        float p = __expf(fminf(e, 80.f));
        uint2 raw = __ldg((const uint2*)(g_h16 + (size_t)src * 64 + cl * 4));
        float2 f0 = __half22float2(*(__half2*)&raw.x);
        float2 f1 = __half22float2(*(__half2*)&raw.y);
        s += p;
        a0 = fmaf(p, f0.x, a0); a1 = fmaf(p, f0.y, a1);
        a2 = fmaf(p, f1.x, a2); a3 = fmaf(p, f1.y, a3);
    }
    s  += __shfl_xor_sync(0xffffffffu, s, 16);
    a0 += __shfl_xor_sync(0xffffffffu, a0, 16);
    a1 += __shfl_xor_sync(0xffffffffu, a1, 16);
    a2 += __shfl_xor_sync(0xffffffffu, a2, 16);
    a3 += __shfl_xor_sync(0xffffffffu, a3, 16);
    if (half == 0) {
        float inv = 1.f / (s + 1e-16f);
        float4 bv = __ldg((const float4*)(B + cl * 4));
        float o0 = a0 * inv + bv.x;
        float o1 = a1 * inv + bv.y;
        float o2 = a2 * inv + bv.z;
        float o3 = a3 * inv + bv.w;
        o0 = (o0 > 0.f) ? o0 : (__expf(o0) - 1.f);   // ELU
        o1 = (o1 > 0.f) ? o1 : (__expf(o1) - 1.f);
        o2 = (o2 > 0.f) ? o2 : (__expf(o2) - 1.f);
        o3 = (o3 > 0.f) ? o3 : (__expf(o3) - 1.f);
        *(float4*)&g_act[(size_t)gw * 64 + cl * 4] = make_float4(o0, o1, o2, o3);
    }
}

// final layer: 1 head, 32 channels; 2 edges/iteration + fused mean-pool
__global__ void k_agg_final(const float* __restrict__ Bf, const int* __restrict__ batch) {
    int gw = (blockIdx.x * blockDim.x + threadIdx.x) >> 5;
    if (gw >= NB) return;
    int lane = threadIdx.x & 31;
    int half = lane >> 4;
    int cl   = lane & 15;           // channels 2cl..2cl+1
    int begin = g_off[gw], end = g_off[gw + 1];
    float ad = g_adst[gw];

    float s = 0.f, a0 = 0.f, a1 = 0.f;
    for (int i = begin + half; i < end; i += 2) {
        int src = __ldg(&g_csr[i]);
        float e = __ldg(&g_asrc[src]) + ad;
        e = (e >= 0.f) ? e : 0.2f * e;
        float p = __expf(fminf(e, 80.f));
        float2 f = __half22float2(__ldg((const __half2*)(g_h16 + (size_t)src * 32 + cl * 2)));
        s += p;
        a0 = fmaf(p, f.x, a0);
        a1 = fmaf(p, f.y, a1);
    }
    s  += __shfl_xor_sync(0xffffffffu, s, 16);
    a0 += __shfl_xor_sync(0xffffffffu, a0, 16);
    a1 += __shfl_xor_sync(0xffffffffu, a1, 16);
    if (half == 0) {
        float inv = 1.f / (s + 1e-16f);
        float o0 = a0 * inv + Bf[cl * 2];
        float o1 = a1 * inv + Bf[cl * 2 + 1];
        int g = batch[gw];
        atomicAdd(&g_pool[g * 32 + cl * 2], o0);
        atomicAdd(&g_pool[g * 32 + cl * 2 + 1], o1);
        if (cl == 0) atomicAdd(&g_cnt[g], 1.f);
    }
}

// ---------------- head ----------------
__global__ void k_final(const float* __restrict__ Wl, const float* __restrict__ bl,
                        float* __restrict__ out) {
    int t = blockIdx.x * blockDim.x + threadIdx.x;
    if (t >= GG * 2) return;
    int g = t >> 1, o = t & 1;
    float cnt = fmaxf(g_cnt[g], 1.f);
    float acc = 0.f;
#pragma unroll
    for (int c = 0; c < 32; c++) acc += g_pool[g * 32 + c] * Wl[c * 2 + o];
    out[t] = acc / cnt + bl[o];
}

// ---------------- launcher ----------------
extern "C" void kernel_launch(void* const* d_in, const int* in_sizes, int n_in,
                              void* d_out, int out_size) {
    const float* x     = (const float*)d_in[0];
    const int*   ei    = (const int*)d_in[1];      // int32
    const int*   batch = (const int*)d_in[2];      // int32
    const float* W0 = (const float*)d_in[3];
    const float* as0 = (const float*)d_in[4];
    const float* ad0 = (const float*)d_in[5];
    const float* b0 = (const float*)d_in[6];
    const float* W1 = (const float*)d_in[7];
    const float* as1 = (const float*)d_in[8];
    const float* ad1 = (const float*)d_in[9];
    const float* b1 = (const float*)d_in[10];
    const float* W2 = (const float*)d_in[11];
    const float* as2 = (const float*)d_in[12];
    const float* ad2 = (const float*)d_in[13];
    const float* b2 = (const float*)d_in[14];
    const float* Wf = (const float*)d_in[15];
    const float* asf = (const float*)d_in[16];
    const float* adf = (const float*)d_in[17];
    const float* bf = (const float*)d_in[18];
    const float* Wl = (const float*)d_in[19];
    const float* bl = (const float*)d_in[20];
    float* out = (float*)d_out;

    const int AGG_GRID = (NB * 32 + 255) / 256;

    // graph prep + layer-0 GEMM (gemm0 is CSR-independent; stays 4th so the
    // fixed ncu window keeps profiling it)
    k_zero<<<(NB + 256) / 256, 256>>>();
    k_count<<<(ET + 255) / 256, 256>>>(ei);
    k_scan<<<1, 1024>>>();
    k_gemm<128, 64, 32, false><<<(NB + 31) / 32, 256>>>(x, W0, as0, ad0);
    k_scatter<<<(ET + 255) / 256, 256>>>(ei);

    // layer 0 aggregate
    k_agg<<<AGG_GRID, 256>>>(b0);
    // layer 1
    k_gemm<64, 64, 64, true><<<(NB + 63) / 64, 256>>>(nullptr, W1, as1, ad1);
    k_agg<<<AGG_GRID, 256>>>(b1);
    // layer 2
    k_gemm<64, 64, 64, true><<<(NB + 63) / 64, 256>>>(nullptr, W2, as2, ad2);
    k_agg<<<AGG_GRID, 256>>>(b2);
    // final conv: 64 -> 32, 1 head
    k_gemm<64, 32, 64, true><<<(NB + 63) / 64, 256>>>(nullptr, Wf, asf, adf);
    k_agg_final<<<AGG_GRID, 256>>>(bf, batch);

    // linear head
    k_final<<<1, 256>>>(Wl, bl, out);
}